// round 4
// baseline (speedup 1.0000x reference)
#include <cuda_runtime.h>
#include <math.h>

// GridPooling: points [B,N,3] f32, features [B,N,F] f32 -> grid [B,32,32,32,F] f32
// B=4, N=100000, F=64, GRID=32.
// Strategy: counting-sort point ids by (batch, voxel), then per-voxel gather-max
// with coalesced reads and ZERO output atomics (R1 showed REDG lane throughput
// was the bottleneck at 79us).
#define GRIDR   32
#define NVOX    (GRIDR * GRIDR * GRIDR)   // 32768
#define NBATCH  4
#define NBINS   (NBATCH * NVOX)           // 131072
#define FDIM    64
#define MAXPTS  400000

__device__ int g_min_bits;
__device__ int g_max_bits;
__device__ int g_gidx[MAXPTS];     // combined bin id (b*32768+vox), -1 if OOB
__device__ int g_rank[MAXPTS];     // rank within bin
__device__ int g_plist[MAXPTS];    // point ids grouped by bin
__device__ int g_cnt[NBINS];       // per-bin count
__device__ int g_partoff[NBINS];   // exclusive offset within 256-bin block
__device__ int g_blockbase[NBINS / 256]; // 512 block bases

__device__ __forceinline__ void atomicMinF(int* addr, float v) {
    if (v >= 0.0f) atomicMin(addr, __float_as_int(v));
    else           atomicMax((unsigned int*)addr, __float_as_uint(v));
}
__device__ __forceinline__ void atomicMaxF(int* addr, float v) {
    if (v >= 0.0f) atomicMax(addr, __float_as_int(v));
    else           atomicMin((unsigned int*)addr, __float_as_uint(v));
}

// K0: zero bin counts + seed min/max. (Output grid no longer needs zeroing:
// the gather kernel writes every voxel.)
__global__ void init_kernel() {
    int i = blockIdx.x * blockDim.x + threadIdx.x;
    if (i < NBINS) g_cnt[i] = 0;
    if (i == 0) {
        g_min_bits = __float_as_int( INFINITY);
        g_max_bits = __float_as_int(-INFINITY);
    }
}

// K1: global min/max over all point coordinates (float4 vectorized).
__global__ void minmax_kernel(const float4* __restrict__ pts, int n4) {
    float lmin =  INFINITY;
    float lmax = -INFINITY;
    int stride = gridDim.x * blockDim.x;
    for (int i = blockIdx.x * blockDim.x + threadIdx.x; i < n4; i += stride) {
        float4 v = pts[i];
        lmin = fminf(lmin, fminf(fminf(v.x, v.y), fminf(v.z, v.w)));
        lmax = fmaxf(lmax, fmaxf(fmaxf(v.x, v.y), fmaxf(v.z, v.w)));
    }
    #pragma unroll
    for (int o = 16; o > 0; o >>= 1) {
        lmin = fminf(lmin, __shfl_xor_sync(0xFFFFFFFFu, lmin, o));
        lmax = fmaxf(lmax, __shfl_xor_sync(0xFFFFFFFFu, lmax, o));
    }
    if ((threadIdx.x & 31) == 0) {
        atomicMinF(&g_min_bits, lmin);
        atomicMaxF(&g_max_bits, lmax);
    }
}

// K2: per-point bin index (exact reference arithmetic) + histogram rank.
__global__ void gidx_kernel(const float* __restrict__ pts, int np, int npb) {
    int p = blockIdx.x * blockDim.x + threadIdx.x;
    if (p >= np) return;
    float pmin  = __int_as_float(g_min_bits);
    float pmax  = __int_as_float(g_max_bits);
    float denom = (pmax - pmin) + 1e-6f;

    float x = pts[p * 3 + 0];
    float y = pts[p * 3 + 1];
    float z = pts[p * 3 + 2];
    int vx = (int)floorf(((x - pmin) / denom) * 32.0f);
    int vy = (int)floorf(((y - pmin) / denom) * 32.0f);
    int vz = (int)floorf(((z - pmin) / denom) * 32.0f);

    if ((unsigned)vx < 32u && (unsigned)vy < 32u && (unsigned)vz < 32u) {
        int b   = p / npb;
        int bin = b * NVOX + vx * (GRIDR * GRIDR) + vy * GRIDR + vz;
        g_gidx[p] = bin;
        g_rank[p] = atomicAdd(&g_cnt[bin], 1);
    } else {
        g_gidx[p] = -1;   // JAX drops OOB scatter indices
    }
}

// K3a: per-256-bin-block exclusive scan (Hillis-Steele in shared mem).
__global__ void scan_block_kernel() {
    __shared__ int s[256];
    int i = blockIdx.x * 256 + threadIdx.x;
    int v = g_cnt[i];
    s[threadIdx.x] = v;
    __syncthreads();
    #pragma unroll
    for (int d = 1; d < 256; d <<= 1) {
        int t = (threadIdx.x >= d) ? s[threadIdx.x - d] : 0;
        __syncthreads();
        s[threadIdx.x] += t;
        __syncthreads();
    }
    g_partoff[i] = s[threadIdx.x] - v;              // exclusive
    if (threadIdx.x == 255) g_blockbase[blockIdx.x] = s[255];  // block sum
}

// K3b: exclusive scan of the 512 block sums (one block).
__global__ void scan_sums_kernel() {
    __shared__ int s[512];
    int v = g_blockbase[threadIdx.x];
    s[threadIdx.x] = v;
    __syncthreads();
    #pragma unroll
    for (int d = 1; d < 512; d <<= 1) {
        int t = (threadIdx.x >= d) ? s[threadIdx.x - d] : 0;
        __syncthreads();
        s[threadIdx.x] += t;
        __syncthreads();
    }
    g_blockbase[threadIdx.x] = s[threadIdx.x] - v;  // exclusive
}

// K4: scatter point ids into per-bin contiguous segments.
__global__ void scatter_ids_kernel(int np) {
    int p = blockIdx.x * blockDim.x + threadIdx.x;
    if (p >= np) return;
    int bin = g_gidx[p];
    if (bin < 0) return;
    int slot = g_partoff[bin] + g_blockbase[bin >> 8] + g_rank[p];
    g_plist[slot] = p;
}

// K5: per-voxel gather-max. 16 lanes per voxel; lane c owns float4 chunk c.
// Feature reads are coalesced 256B per point per half-warp; plain store.
// acc starts at 0 == reference's zero-initialized grid max.
__global__ void gather_kernel(const float4* __restrict__ feat,
                              float4* __restrict__ out) {
    int t = blockIdx.x * blockDim.x + threadIdx.x;   // NBINS*16 threads
    int v = t >> 4;
    int c = t & 15;
    int k = g_cnt[v];
    float4 acc = make_float4(0.f, 0.f, 0.f, 0.f);
    if (k > 0) {
        int base = g_partoff[v] + g_blockbase[v >> 8];
        int p = g_plist[base];                       // prefetch first id
        for (int i = 1; i < k; i++) {
            int pn = g_plist[base + i];              // prefetch next id
            float4 f = feat[p * 16 + c];
            acc.x = fmaxf(acc.x, f.x);
            acc.y = fmaxf(acc.y, f.y);
            acc.z = fmaxf(acc.z, f.z);
            acc.w = fmaxf(acc.w, f.w);
            p = pn;
        }
        float4 f = feat[p * 16 + c];
        acc.x = fmaxf(acc.x, f.x);
        acc.y = fmaxf(acc.y, f.y);
        acc.z = fmaxf(acc.z, f.z);
        acc.w = fmaxf(acc.w, f.w);
    }
    out[t] = acc;   // layout [B,32768,64] floats == [bin][16] float4s
}

extern "C" void kernel_launch(void* const* d_in, const int* in_sizes, int n_in,
                              void* d_out, int out_size) {
    const float* points   = (const float*)d_in[0];   // B*N*3
    const float* features = (const float*)d_in[1];   // B*N*64

    int np  = in_sizes[0] / 3;          // total points = B*N
    int npb = np / NBATCH;              // points per batch

    // K0: reset counts + min/max seeds
    init_kernel<<<NBINS / 256, 256>>>();
    // K1: global min/max
    {
        int n4 = in_sizes[0] / 4;       // 1.2M floats -> 300k float4
        minmax_kernel<<<1024, 256>>>((const float4*)points, n4);
    }
    // K2: bin index + histogram rank
    gidx_kernel<<<(np + 255) / 256, 256>>>(points, np, npb);
    // K3: two-level exclusive scan of bin counts
    scan_block_kernel<<<NBINS / 256, 256>>>();
    scan_sums_kernel<<<1, NBINS / 256>>>();
    // K4: group point ids by bin
    scatter_ids_kernel<<<(np + 255) / 256, 256>>>(np);
    // K5: per-voxel gather-max (writes every voxel; no atomics, no pre-zero)
    {
        int total = NBINS * 16;
        gather_kernel<<<total / 256, 256>>>((const float4*)features,
                                            (float4*)d_out);
    }
}

// round 6
// speedup vs baseline: 1.4346x; 1.4346x over previous
#include <cuda_runtime.h>
#include <math.h>

// GridPooling: points [B,N,3] f32, features [B,N,F] f32 -> grid [B,32,32,32,F] f32
// B=4, N=100000, F=64, GRID=32.
// Counting-sort point ids by (batch,voxel), then per-voxel gather-max with
// zero output atomics. Gather critical path (hottest voxel ~200 pts) is
// attacked with 8x unroll (MLP) and a 2-way sub-split per voxel.
#define GRIDR   32
#define NVOX    (GRIDR * GRIDR * GRIDR)   // 32768
#define NBATCH  4
#define NBINS   (NBATCH * NVOX)           // 131072
#define FDIM    64
#define MAXPTS  400000

__device__ int g_min_bits;
__device__ int g_max_bits;
__device__ int g_gidx[MAXPTS];     // combined bin id (b*32768+vox), -1 if OOB
__device__ int g_rank[MAXPTS];     // rank within bin
__device__ int g_plist[MAXPTS];    // point ids grouped by bin
__device__ int g_cnt[NBINS];       // per-bin count
__device__ int g_partoff[NBINS];   // exclusive offset within 256-bin block
__device__ int g_blockbase[NBINS / 256]; // 512 block bases

__device__ __forceinline__ void atomicMinF(int* addr, float v) {
    if (v >= 0.0f) atomicMin(addr, __float_as_int(v));
    else           atomicMax((unsigned int*)addr, __float_as_uint(v));
}
__device__ __forceinline__ void atomicMaxF(int* addr, float v) {
    if (v >= 0.0f) atomicMax(addr, __float_as_int(v));
    else           atomicMin((unsigned int*)addr, __float_as_uint(v));
}
__device__ __forceinline__ void fmax4(float4& a, const float4& b) {
    a.x = fmaxf(a.x, b.x); a.y = fmaxf(a.y, b.y);
    a.z = fmaxf(a.z, b.z); a.w = fmaxf(a.w, b.w);
}

// K0: zero bin counts + seed min/max.
__global__ void init_kernel() {
    int i = blockIdx.x * blockDim.x + threadIdx.x;
    if (i < NBINS) g_cnt[i] = 0;
    if (i == 0) {
        g_min_bits = __float_as_int( INFINITY);
        g_max_bits = __float_as_int(-INFINITY);
    }
}

// K1: global min/max over all point coordinates (float4 vectorized).
__global__ void minmax_kernel(const float4* __restrict__ pts, int n4) {
    float lmin =  INFINITY;
    float lmax = -INFINITY;
    int stride = gridDim.x * blockDim.x;
    for (int i = blockIdx.x * blockDim.x + threadIdx.x; i < n4; i += stride) {
        float4 v = pts[i];
        lmin = fminf(lmin, fminf(fminf(v.x, v.y), fminf(v.z, v.w)));
        lmax = fmaxf(lmax, fmaxf(fmaxf(v.x, v.y), fmaxf(v.z, v.w)));
    }
    #pragma unroll
    for (int o = 16; o > 0; o >>= 1) {
        lmin = fminf(lmin, __shfl_xor_sync(0xFFFFFFFFu, lmin, o));
        lmax = fmaxf(lmax, __shfl_xor_sync(0xFFFFFFFFu, lmax, o));
    }
    if ((threadIdx.x & 31) == 0) {
        atomicMinF(&g_min_bits, lmin);
        atomicMaxF(&g_max_bits, lmax);
    }
}

// K2: per-point bin index (exact reference arithmetic) + histogram rank.
__global__ void gidx_kernel(const float* __restrict__ pts, int np, int npb) {
    int p = blockIdx.x * blockDim.x + threadIdx.x;
    if (p >= np) return;
    float pmin  = __int_as_float(g_min_bits);
    float pmax  = __int_as_float(g_max_bits);
    float denom = (pmax - pmin) + 1e-6f;

    float x = pts[p * 3 + 0];
    float y = pts[p * 3 + 1];
    float z = pts[p * 3 + 2];
    int vx = (int)floorf(((x - pmin) / denom) * 32.0f);
    int vy = (int)floorf(((y - pmin) / denom) * 32.0f);
    int vz = (int)floorf(((z - pmin) / denom) * 32.0f);

    if ((unsigned)vx < 32u && (unsigned)vy < 32u && (unsigned)vz < 32u) {
        int b   = p / npb;
        int bin = b * NVOX + vx * (GRIDR * GRIDR) + vy * GRIDR + vz;
        g_gidx[p] = bin;
        g_rank[p] = atomicAdd(&g_cnt[bin], 1);
    } else {
        g_gidx[p] = -1;   // JAX drops OOB scatter indices
    }
}

// K3a: per-256-bin-block exclusive scan (shfl-based, 2 syncs).
__global__ void scan_block_kernel() {
    __shared__ int wsum[8];
    int i = blockIdx.x * 256 + threadIdx.x;
    int lane = threadIdx.x & 31;
    int w    = threadIdx.x >> 5;
    int v = g_cnt[i];
    int x = v;
    #pragma unroll
    for (int d = 1; d < 32; d <<= 1) {
        int t = __shfl_up_sync(0xFFFFFFFFu, x, d);
        if (lane >= d) x += t;
    }
    if (lane == 31) wsum[w] = x;
    __syncthreads();
    if (w == 0 && lane < 8) {
        int y = wsum[lane];
        #pragma unroll
        for (int d = 1; d < 8; d <<= 1) {
            int t = __shfl_up_sync(0xFFu, y, d);
            if (lane >= d) y += t;
        }
        wsum[lane] = y;
    }
    __syncthreads();
    int off = (w > 0) ? wsum[w - 1] : 0;
    g_partoff[i] = off + x - v;                    // exclusive
    if (threadIdx.x == 255) g_blockbase[blockIdx.x] = off + x;
}

// K3b: exclusive scan of the 512 block sums (one block, shfl-based).
__global__ void scan_sums_kernel() {
    __shared__ int wsum[16];
    int lane = threadIdx.x & 31;
    int w    = threadIdx.x >> 5;
    int v = g_blockbase[threadIdx.x];
    int x = v;
    #pragma unroll
    for (int d = 1; d < 32; d <<= 1) {
        int t = __shfl_up_sync(0xFFFFFFFFu, x, d);
        if (lane >= d) x += t;
    }
    if (lane == 31) wsum[w] = x;
    __syncthreads();
    if (w == 0 && lane < 16) {
        int y = wsum[lane];
        #pragma unroll
        for (int d = 1; d < 16; d <<= 1) {
            int t = __shfl_up_sync(0xFFFFu, y, d);
            if (lane >= d) y += t;
        }
        wsum[lane] = y;
    }
    __syncthreads();
    int off = (w > 0) ? wsum[w - 1] : 0;
    g_blockbase[threadIdx.x] = off + x - v;        // exclusive
}

// K4: scatter point ids into per-bin contiguous segments.
__global__ void scatter_ids_kernel(int np) {
    int p = blockIdx.x * blockDim.x + threadIdx.x;
    if (p >= np) return;
    int bin = g_gidx[p];
    if (bin < 0) return;
    int slot = g_partoff[bin] + g_blockbase[bin >> 8] + g_rank[p];
    g_plist[slot] = p;
}

// K5: per-voxel gather-max. One WARP per voxel: 2 subs x 16 chunks.
// Sub s handles sorted indices {s, s+2, ...}; 8x unroll keeps 8 feature
// loads in flight per thread. Half-warp reads one point's contiguous 256B.
// Final combine: shfl_xor(16). acc starts at 0 == reference zero-init max.
__global__ void gather_kernel(const float4* __restrict__ feat,
                              float4* __restrict__ out) {
    int t = blockIdx.x * blockDim.x + threadIdx.x;   // NBINS*32 threads
    int v    = t >> 5;
    int lane = t & 31;
    int s    = lane >> 4;       // sub 0/1
    int c    = lane & 15;       // float4 chunk
    int k = g_cnt[v];
    float4 acc = make_float4(0.f, 0.f, 0.f, 0.f);
    if (k > 0) {
        int base = g_partoff[v] + g_blockbase[v >> 8];
        int i = s;
        // unrolled: 8 points per sub per iteration (stride 2 within sub)
        for (; i + 14 < k; i += 16) {
            int p0 = g_plist[base + i];
            int p1 = g_plist[base + i +  2];
            int p2 = g_plist[base + i +  4];
            int p3 = g_plist[base + i +  6];
            int p4 = g_plist[base + i +  8];
            int p5 = g_plist[base + i + 10];
            int p6 = g_plist[base + i + 12];
            int p7 = g_plist[base + i + 14];
            float4 f0 = feat[p0 * 16 + c];
            float4 f1 = feat[p1 * 16 + c];
            float4 f2 = feat[p2 * 16 + c];
            float4 f3 = feat[p3 * 16 + c];
            float4 f4 = feat[p4 * 16 + c];
            float4 f5 = feat[p5 * 16 + c];
            float4 f6 = feat[p6 * 16 + c];
            float4 f7 = feat[p7 * 16 + c];
            fmax4(f0, f1); fmax4(f2, f3); fmax4(f4, f5); fmax4(f6, f7);
            fmax4(f0, f2); fmax4(f4, f6);
            fmax4(f0, f4);
            fmax4(acc, f0);
        }
        for (; i < k; i += 2) {
            float4 f = feat[g_plist[base + i] * 16 + c];
            fmax4(acc, f);
        }
    }
    // combine the two subs (all 32 lanes converged here)
    acc.x = fmaxf(acc.x, __shfl_xor_sync(0xFFFFFFFFu, acc.x, 16));
    acc.y = fmaxf(acc.y, __shfl_xor_sync(0xFFFFFFFFu, acc.y, 16));
    acc.z = fmaxf(acc.z, __shfl_xor_sync(0xFFFFFFFFu, acc.z, 16));
    acc.w = fmaxf(acc.w, __shfl_xor_sync(0xFFFFFFFFu, acc.w, 16));
    if (s == 0) out[v * 16 + c] = acc;   // [bin][16] float4s == [B,32^3,64] f32
}

extern "C" void kernel_launch(void* const* d_in, const int* in_sizes, int n_in,
                              void* d_out, int out_size) {
    const float* points   = (const float*)d_in[0];   // B*N*3
    const float* features = (const float*)d_in[1];   // B*N*64

    int np  = in_sizes[0] / 3;          // total points = B*N
    int npb = np / NBATCH;              // points per batch

    init_kernel<<<NBINS / 256, 256>>>();
    {
        int n4 = in_sizes[0] / 4;       // 1.2M floats -> 300k float4
        minmax_kernel<<<1024, 256>>>((const float4*)points, n4);
    }
    gidx_kernel<<<(np + 255) / 256, 256>>>(points, np, npb);
    scan_block_kernel<<<NBINS / 256, 256>>>();
    scan_sums_kernel<<<1, NBINS / 256>>>();
    scatter_ids_kernel<<<(np + 255) / 256, 256>>>(np);
    {
        long long total = (long long)NBINS * 32;    // warp per voxel
        gather_kernel<<<(int)(total / 256), 256>>>((const float4*)features,
                                                   (float4*)d_out);
    }
}